// round 17
// baseline (speedup 1.0000x reference)
#include <cuda_runtime.h>
#include <cuda_fp16.h>
#include <stdint.h>

#define NB   2
#define SEQ  2048
#define DM   1024
#define NH   16
#define DKH  64

// ===================== device scratch (no allocations) =====================
__device__ __align__(16) __half g_xq[(size_t)NB*SEQ*DM];
__device__ __align__(16) __half g_xk[(size_t)NB*SEQ*DM];
__device__ __align__(16) __half g_xv[(size_t)NB*SEQ*DM];
__device__ __align__(16) __half g_wq[(size_t)DM*DM];
__device__ __align__(16) __half g_wk[(size_t)DM*DM];
__device__ __align__(16) __half g_wv[(size_t)DM*DM];
__device__ __align__(16) __half g_wo[(size_t)DM*DM];
__device__ __align__(16) __half g_q[(size_t)NB*NH*SEQ*DKH];     // pre-scaled by 0.125*log2(e)
__device__ __align__(16) __half g_k[(size_t)NB*NH*SEQ*DKH];
__device__ __align__(16) __half g_vT[(size_t)NB*NH*DKH*SEQ];
__device__ __align__(16) __half g_ctx[(size_t)NB*SEQ*DM];
__device__ uint32_t g_mbits[(size_t)NB*SEQ*64];   // [n][q][kv/32], bit=1 -> masked

// ===================== helpers =====================
__device__ __forceinline__ uint32_t smem_u32(const void* p) {
    uint32_t a;
    asm("{ .reg .u64 t; cvta.to.shared.u64 t, %1; cvt.u32.u64 %0, t; }" : "=r"(a) : "l"(p));
    return a;
}
__device__ __forceinline__ void ldsm4(uint32_t* r, uint32_t a) {
    asm volatile("ldmatrix.sync.aligned.m8n8.x4.shared.b16 {%0,%1,%2,%3}, [%4];"
        : "=r"(r[0]), "=r"(r[1]), "=r"(r[2]), "=r"(r[3]) : "r"(a));
}
__device__ __forceinline__ void mma_fp16(float* d, const uint32_t* a, uint32_t b0, uint32_t b1) {
    asm volatile(
        "mma.sync.aligned.m16n8k16.row.col.f32.f16.f16.f32 "
        "{%0,%1,%2,%3}, {%4,%5,%6,%7}, {%8,%9}, {%0,%1,%2,%3};"
        : "+f"(d[0]), "+f"(d[1]), "+f"(d[2]), "+f"(d[3])
        : "r"(a[0]), "r"(a[1]), "r"(a[2]), "r"(a[3]), "r"(b0), "r"(b1));
}
// pack two f32 into half2 (lo = l, hi = h)
__device__ __forceinline__ uint32_t cvt2h(float h, float l) {
    uint32_t d;
    asm("cvt.rn.f16x2.f32 %0, %1, %2;" : "=r"(d) : "f"(h), "f"(l));
    return d;
}
__device__ __forceinline__ uint32_t ex2h2(uint32_t x) {
    uint32_t d;
    asm("ex2.approx.f16x2 %0, %1;" : "=r"(d) : "r"(x));
    return d;
}
__device__ __forceinline__ uint32_t hadd2(uint32_t a, uint32_t b) {
    uint32_t d;
    asm("add.rn.f16x2 %0, %1, %2;" : "=r"(d) : "r"(a), "r"(b));
    return d;
}
// AND-pattern: halfword k is 0xFFFF where mask bit (sh+k) is SET (masked)
__device__ __forceinline__ uint32_t zmask2(uint32_t w, int sh) {
    uint32_t t = w >> sh;
    return (t & 1u) * 0x0000FFFFu + (t & 2u) * 0x7FFF8000u;
}
#define CP16(dst, src)  asm volatile("cp.async.cg.shared.global [%0], [%1], 16;" :: "r"(dst), "l"(src) : "memory")
#define CPCOMMIT()      asm volatile("cp.async.commit_group;" ::: "memory")
#define CPWAIT0()       asm volatile("cp.async.wait_group 0;" ::: "memory")

// 128-byte rows: SW128 swizzle on 16B chunks
#define ASWZ(r, ch) ((uint32_t)(((r) << 7) + ((((ch) ^ ((r) & 7))) << 4)))

__device__ __forceinline__ uint32_t pack2h(float a, float b) {
    __half2 h = __floats2half2_rn(a, b);
    return *(uint32_t*)&h;
}
__device__ __forceinline__ float2 h2f2(uint32_t u) {
    return __half22float2(*(__half2*)&u);
}

// ===================== prep: ONE fused convert + maskpack kernel =====================
#define INP4 (NB * SEQ * DM / 4)     // 1048576 float4 per input
#define W4   (DM * DM / 4)           // 262144 per weight
#define TOT4 (3 * INP4 + 4 * W4)     // 4194304
#define MW   (NB * SEQ * 64)         // 262144 mask words

__global__ void prep_kernel(
    const float* __restrict__ q,  const float* __restrict__ k,  const float* __restrict__ v,
    const float* __restrict__ Wq, const float* __restrict__ Wk, const float* __restrict__ Wv,
    const float* __restrict__ Wo, const int* __restrict__ mask)
{
    int gid = blockIdx.x * blockDim.x + threadIdx.x;
    if (gid < TOT4) {
        const float* src;
        __half* dst;
        int off;
        if (gid < 3 * INP4) {
            int seg = gid / INP4;
            off = gid - seg * INP4;
            src = (seg == 0) ? q : (seg == 1) ? k : v;
            dst = (seg == 0) ? g_xq : (seg == 1) ? g_xk : g_xv;
        } else {
            int r = gid - 3 * INP4;
            int seg = r / W4;
            off = r - seg * W4;
            src = (seg == 0) ? Wq : (seg == 1) ? Wk : (seg == 2) ? Wv : Wo;
            dst = (seg == 0) ? g_wq : (seg == 1) ? g_wk : (seg == 2) ? g_wv : g_wo;
        }
        float4 x = ((const float4*)src)[off];
        uint2 o;
        o.x = pack2h(x.x, x.y);
        o.y = pack2h(x.z, x.w);
        ((uint2*)dst)[off] = o;
    } else {
        int w = gid - TOT4;
        if (w >= MW) return;
        const int* p = mask + (size_t)w * 32;
        uint32_t bits = 0;
#pragma unroll
        for (int j = 0; j < 32; j += 4) {
            int4 m4 = *(const int4*)(p + j);
            bits |= (m4.x ? 1u : 0u) << j       | (m4.y ? 1u : 0u) << (j + 1)
                  | (m4.z ? 1u : 0u) << (j + 2) | (m4.w ? 1u : 0u) << (j + 3);
        }
        g_mbits[w] = bits;
    }
}

// ===================== projection GEMM core (2-stage cp.async, de-phased) =====================
#define PROJ_SMEM 65536

__device__ __forceinline__ void proj_load(
    uint32_t sbase, int tid, int k0,
    const __half* __restrict__ A, const __half* __restrict__ W, int bm, int bn)
{
#pragma unroll
    for (int i = 0; i < 4; i++) {
        int idx = tid + i * 256;          // 0..1023 -> 128 rows x 8 chunks
        int r = idx >> 3, ch = idx & 7;
        uint32_t d = sbase + ASWZ(r, ch);
        CP16(d,         A + (size_t)(bm + r) * DM + k0 + ch * 8);
        CP16(d + 16384, W + (size_t)(bn + r) * DM + k0 + ch * 8);
    }
}

__device__ __forceinline__ void proj_mainloop(
    uint32_t sb, int tid, int lane, int warp, int c0,
    const __half* __restrict__ A, const __half* __restrict__ W,
    int bm, int bn, float acc[4][4][4])
{
    int wm = (warp >> 2) * 64;
    int wn = (warp & 3) * 32;
    int a_r = (lane & 7) + ((lane >> 3) & 1) * 8;
    int a_c = lane >> 4;
    int b_r = (lane & 7) + (lane >> 4) * 8;
    int b_c = (lane >> 3) & 1;

    proj_load(sb, tid, c0 * 64, A, W, bm, bn);
    CPCOMMIT();

    for (int c = 0; c < 16; c++) {
        CPWAIT0();
        __syncthreads();
        if (c + 1 < 16) {
            int cr = (c + 1 + c0) & 15;
            proj_load(sb + ((c + 1) & 1) * 32768, tid, cr * 64, A, W, bm, bn);
            CPCOMMIT();
        }
        uint32_t ab = sb + (c & 1) * 32768;
        uint32_t wb = ab + 16384;
#pragma unroll
        for (int k16 = 0; k16 < 4; k16++) {
            uint32_t bh0[4], bh1[4];
            ldsm4(bh0, wb + ASWZ(wn + b_r,      k16 * 2 + b_c));
            ldsm4(bh1, wb + ASWZ(wn + 16 + b_r, k16 * 2 + b_c));
#pragma unroll
            for (int mt = 0; mt < 4; mt++) {
                uint32_t ah[4];
                ldsm4(ah, ab + ASWZ(wm + mt * 16 + a_r, k16 * 2 + a_c));
                mma_fp16(acc[mt][0], ah, bh0[0], bh0[1]);
                mma_fp16(acc[mt][1], ah, bh0[2], bh0[3]);
                mma_fp16(acc[mt][2], ah, bh1[0], bh1[1]);
                mma_fp16(acc[mt][3], ah, bh1[2], bh1[3]);
            }
        }
    }
}

// ---- fused Q/K/V projection: grid.z selects which ----
__global__ void __launch_bounds__(256, 2) proj_qkv_kernel(
    const float* __restrict__ bq, const float* __restrict__ bk, const float* __restrict__ bv)
{
    int z = blockIdx.z;
    const __half* A = (z == 0) ? g_xq : (z == 1) ? g_xk : g_xv;
    const __half* W = (z == 0) ? g_wq : (z == 1) ? g_wk : g_wv;
    const float* bias = (z == 0) ? bq : (z == 1) ? bk : bv;
    __half* out = (z == 0) ? g_q : (z == 1) ? g_k : g_vT;
    float scale = (z == 0) ? 0.18033688011112043f : 1.0f;   // 0.125 * log2(e) for Q

    extern __shared__ __align__(128) char smem[];
    uint32_t sb = smem_u32(smem);
    int tid = threadIdx.x, lane = tid & 31, warp = tid >> 5;
    int bm = blockIdx.y * 128, bn = blockIdx.x * 128;
    int fbid = blockIdx.x + (blockIdx.y << 3) + (blockIdx.z << 8);
    int c0 = ((fbid / 148) & 1) << 3;     // de-phase co-resident CTAs

    float acc[4][4][4];
#pragma unroll
    for (int i = 0; i < 4; i++)
#pragma unroll
        for (int j = 0; j < 4; j++)
#pragma unroll
            for (int t = 0; t < 4; t++) acc[i][j][t] = 0.0f;

    proj_mainloop(sb, tid, lane, warp, c0, A, W, bm, bn, acc);

    int wm = (warp >> 2) * 64, wn = (warp & 3) * 32;
    int lr = lane >> 2, lc = (lane & 3) * 2;

    if (z < 2) {
        // Q/K: direct 4B stores, head-major [n][h][q][d]
#pragma unroll
        for (int mt = 0; mt < 4; mt++) {
#pragma unroll
            for (int i = 0; i < 2; i++) {
                int m = bm + wm + mt * 16 + lr + i * 8;
                int nb2 = m >> 11, qrow = m & (SEQ - 1);
#pragma unroll
                for (int nt = 0; nt < 4; nt++) {
                    int o = bn + wn + nt * 8 + lc;
                    float v0 = (acc[mt][nt][2 * i + 0] + __ldg(bias + o))     * scale;
                    float v1 = (acc[mt][nt][2 * i + 1] + __ldg(bias + o + 1)) * scale;
                    int hh = o >> 6, dd = o & 63;
                    size_t off = ((size_t)(nb2 * NH + hh) * SEQ + qrow) * DKH + dd;
                    *(uint32_t*)(out + off) = pack2h(v0, v1);
                }
            }
        }
    } else {
        // V: transpose via smem, then coalesced 16B row stores to vT [n][h][d][q]
        __syncthreads();   // mainloop smem reads done in all warps
        __half* stg = (__half*)smem;            // [128 dd][stride 132] halves
#pragma unroll
        for (int mt = 0; mt < 4; mt++) {
#pragma unroll
            for (int i = 0; i < 2; i++) {
                int qq_l = wm + mt * 16 + lr + i * 8;     // local q row 0..127
#pragma unroll
                for (int nt = 0; nt < 4; nt++) {
                    int dd_l = wn + nt * 8 + lc;          // local col 0..127
                    int o = bn + dd_l;
                    float v0 = acc[mt][nt][2 * i + 0] + __ldg(bias + o);
                    float v1 = acc[mt][nt][2 * i + 1] + __ldg(bias + o + 1);
                    stg[(dd_l + 0) * 132 + qq_l] = __float2half_rn(v0);
                    stg[(dd_l + 1) * 132 + qq_l] = __float2half_rn(v1);
                }
            }
        }
        __syncthreads();
        int row = tid >> 1;                  // dd_local 0..127
        int seg = (tid & 1) * 64;            // q half
        int o = bn + row;
        int hh = o >> 6, dd = o & 63;
        int nb2 = bm >> 11, qbase = bm & (SEQ - 1);
        __half* dst = out + ((size_t)(nb2 * NH + hh) * DKH + dd) * SEQ + qbase + seg;
        const __half* srcp = stg + row * 132 + seg;
#pragma unroll
        for (int j = 0; j < 64; j += 8) {
            uint2 a = *(const uint2*)(srcp + j);
            uint2 b = *(const uint2*)(srcp + j + 4);
            uint4 w4v;
            w4v.x = a.x; w4v.y = a.y; w4v.z = b.x; w4v.w = b.y;
            *(uint4*)(dst + j) = w4v;
        }
    }
}

// ---- O projection: fp32 output ----
__global__ void __launch_bounds__(256, 2) proj_o_kernel(const float* __restrict__ bias,
                                                        float* __restrict__ out)
{
    extern __shared__ __align__(128) char smem[];
    uint32_t sb = smem_u32(smem);
    int tid = threadIdx.x, lane = tid & 31, warp = tid >> 5;
    int bm = blockIdx.y * 128, bn = blockIdx.x * 128;
    int fbid = blockIdx.x + (blockIdx.y << 3);
    int c0 = ((fbid / 148) & 1) << 3;

    float acc[4][4][4];
#pragma unroll
    for (int i = 0; i < 4; i++)
#pragma unroll
        for (int j = 0; j < 4; j++)
#pragma unroll
            for (int t = 0; t < 4; t++) acc[i][j][t] = 0.0f;

    proj_mainloop(sb, tid, lane, warp, c0, g_ctx, g_wo, bm, bn, acc);

    int wm = (warp >> 2) * 64, wn = (warp & 3) * 32;
    int lr = lane >> 2, lc = (lane & 3) * 2;
#pragma unroll
    for (int mt = 0; mt < 4; mt++) {
#pragma unroll
        for (int i = 0; i < 2; i++) {
            int m = bm + wm + mt * 16 + lr + i * 8;
#pragma unroll
            for (int nt = 0; nt < 4; nt++) {
                int o = bn + wn + nt * 8 + lc;
                float v0 = acc[mt][nt][2 * i + 0] + __ldg(bias + o);
                float v1 = acc[mt][nt][2 * i + 1] + __ldg(bias + o + 1);
                *(float2*)(out + (size_t)m * DM + o) = make_float2(v0, v1);
            }
        }
    }
}

// ===================== attention (32-row warps, de-phased; lsum via HADD2) =====================
// CTA = 128 q rows x 1 head, 4 warps x 32 rows. KV tiles of 64, 2-stage cp.async.
// Co-resident CTAs start the KV sweep 16 tiles apart (sum order is free).
// Q pre-scaled by 0.125*log2(e). Softmax: f32->f16x2 cvt, ex2.approx.f16x2,
// masked entries zeroed post-exp. Row sums: HADD2 spa accumulation (FMA pipe),
// per-tile f32 promote, quad-shuffle in epilogue — zero extra MMAs.
#define ATT_SMEM (16384 + 2 * 16384)

__device__ __forceinline__ void att_load_kv(
    uint32_t sbase, int tid, int kt,
    const __half* __restrict__ kk, const __half* __restrict__ vv)
{
#pragma unroll
    for (int i = 0; i < 4; i++) {
        int idx = tid + i * 128;          // 0..511 -> 64 rows x 8 chunks
        int r = idx >> 3, ch = idx & 7;
        uint32_t d = sbase + ASWZ(r, ch);
        CP16(d,        kk + (size_t)(kt * 64 + r) * DKH + ch * 8);
        CP16(d + 8192, vv + (size_t)r * SEQ + kt * 64 + ch * 8);
    }
}

__global__ void __launch_bounds__(128, 2) attn_kernel()
{
    extern __shared__ __align__(128) char smem[];
    uint32_t sb = smem_u32(smem);
    int tid = threadIdx.x, lane = tid & 31, warp = tid >> 5;   // warp 0..3
    int qt = blockIdx.x, h = blockIdx.y, n = blockIdx.z;
    int fbid = blockIdx.x + (blockIdx.y << 4) + (blockIdx.z << 8);
    int kt0 = ((fbid / 148) & 1) << 4;    // de-phase co-resident CTAs

    const __half* qp = g_q  + ((size_t)(n * NH + h) * SEQ + qt * 128) * DKH;
    const __half* kp = g_k  + (size_t)(n * NH + h) * SEQ * DKH;
    const __half* vp = g_vT + (size_t)(n * NH + h) * DKH * SEQ;
    const uint32_t* mbase = g_mbits + (size_t)n * SEQ * 64;

    // Q tile @0 + KV tile kt0 -> one cp.async group
#pragma unroll
    for (int i = 0; i < 8; i++) {
        int idx = tid + i * 128;          // 0..1023 -> 128 rows x 8 chunks
        int r = idx >> 3, ch = idx & 7;
        CP16(sb + ASWZ(r, ch), qp + (size_t)r * DKH + ch * 8);
    }
    att_load_kv(sb + 16384, tid, kt0, kp, vp);
    CPCOMMIT();

    int a_r = (lane & 7) + ((lane >> 3) & 1) * 8;
    int a_c = lane >> 4;
    int b_r = (lane & 7) + (lane >> 4) * 8;
    int b_c = (lane >> 3) & 1;
    int lr = lane >> 2, lc = (lane & 3) * 2;
    int q0 = qt * 128 + warp * 32 + lr;

    uint32_t qa[4][2][4];                 // [k16][mfrag][reg]
    float oacc[2][8][4];
    float lsumf[2][2];                    // f32 row-sum accumulators
#pragma unroll
    for (int mi = 0; mi < 2; mi++) {
#pragma unroll
        for (int ng = 0; ng < 8; ng++)
#pragma unroll
            for (int t = 0; t < 4; t++) oacc[mi][ng][t] = 0.0f;
        lsumf[mi][0] = 0.0f;
        lsumf[mi][1] = 0.0f;
    }

    for (int kt = 0; kt < 32; kt++) {
        int ktr = (kt + kt0) & 31;        // actual KV tile
        CPWAIT0();
        __syncthreads();
        if (kt == 0) {
#pragma unroll
            for (int k16 = 0; k16 < 4; k16++)
#pragma unroll
                for (int mi = 0; mi < 2; mi++)
                    ldsm4(qa[k16][mi], sb + ASWZ(warp * 32 + mi * 16 + a_r, k16 * 2 + a_c));
        }
        // prefetch mask words (rows lr, lr+8 of each 16-row m-frag)
        uint2 mw[2][2];
#pragma unroll
        for (int mi = 0; mi < 2; mi++)
#pragma unroll
            for (int ri = 0; ri < 2; ri++)
                mw[mi][ri] = *(const uint2*)(mbase + (size_t)(q0 + mi * 16 + ri * 8) * 64 + 2 * ktr);

        if (kt + 1 < 32) {
            att_load_kv(sb + 16384 + ((kt + 1) & 1) * 16384, tid, (kt + 1 + kt0) & 31, kp, vp);
            CPCOMMIT();
        }
        uint32_t kvb = sb + 16384 + (kt & 1) * 16384;

        // ---- S = Q K^T (full tile: 16 independent accumulator chains) ----
        float sacc[2][8][4];
#pragma unroll
        for (int mi = 0; mi < 2; mi++)
#pragma unroll
            for (int ng = 0; ng < 8; ng++)
#pragma unroll
                for (int t = 0; t < 4; t++) sacc[mi][ng][t] = 0.0f;

#pragma unroll
        for (int k16 = 0; k16 < 4; k16++) {
#pragma unroll
            for (int ngp = 0; ngp < 4; ngp++) {
                uint32_t bh[4];
                ldsm4(bh, kvb + ASWZ(ngp * 16 + b_r, k16 * 2 + b_c));
                mma_fp16(sacc[0][2 * ngp],     qa[k16][0], bh[0], bh[1]);
                mma_fp16(sacc[0][2 * ngp + 1], qa[k16][0], bh[2], bh[3]);
                mma_fp16(sacc[1][2 * ngp],     qa[k16][1], bh[0], bh[1]);
                mma_fp16(sacc[1][2 * ngp + 1], qa[k16][1], bh[2], bh[3]);
            }
        }

        // ---- softmax (f16x2 ex2, zero-mask) + PV; lsum via HADD2 (no MMAs) ----
        uint32_t spa[2][4] = {{0u,0u,0u,0u},{0u,0u,0u,0u}};   // per-tile f16x2 sums
#pragma unroll
        for (int g = 0; g < 4; g++) {
            uint32_t pa[2][4];
#pragma unroll
            for (int mi = 0; mi < 2; mi++) {
                uint32_t w0 = (g < 2) ? mw[mi][0].x : mw[mi][0].y;
                uint32_t w1 = (g < 2) ? mw[mi][1].x : mw[mi][1].y;
                int sh = ((g & 1) << 4) + lc;
                const float* s0 = sacc[mi][2 * g];
                const float* s1 = sacc[mi][2 * g + 1];
                pa[mi][0] = ex2h2(cvt2h(s0[1], s0[0])) & ~zmask2(w0, sh);
                pa[mi][1] = ex2h2(cvt2h(s0[3], s0[2])) & ~zmask2(w1, sh);
                pa[mi][2] = ex2h2(cvt2h(s1[1], s1[0])) & ~zmask2(w0, sh + 8);
                pa[mi][3] = ex2h2(cvt2h(s1[3], s1[2])) & ~zmask2(w1, sh + 8);
                spa[mi][0] = hadd2(spa[mi][0], pa[mi][0]);
                spa[mi][1] = hadd2(spa[mi][1], pa[mi][1]);
                spa[mi][2] = hadd2(spa[mi][2], pa[mi][2]);
                spa[mi][3] = hadd2(spa[mi][3], pa[mi][3]);
            }
#pragma unroll
            for (int ngd = 0; ngd < 4; ngd++) {
                uint32_t bh[4];
                ldsm4(bh, kvb + 8192 + ASWZ(ngd * 16 + b_r, g * 2 + b_c));
                mma_fp16(oacc[0][2 * ngd],     pa[0], bh[0], bh[1]);
                mma_fp16(oacc[0][2 * ngd + 1], pa[0], bh[2], bh[3]);
                mma_fp16(oacc[1][2 * ngd],     pa[1], bh[0], bh[1]);
                mma_fp16(oacc[1][2 * ngd + 1], pa[1], bh[2], bh[3]);
            }
        }
        // promote per-tile f16 partials to f32 (rows lr: pa0/pa2; rows lr+8: pa1/pa3)
#pragma unroll
        for (int mi = 0; mi < 2; mi++) {
            float2 a0 = h2f2(spa[mi][0]), a2 = h2f2(spa[mi][2]);
            float2 a1 = h2f2(spa[mi][1]), a3 = h2f2(spa[mi][3]);
            lsumf[mi][0] += (a0.x + a0.y) + (a2.x + a2.y);
            lsumf[mi][1] += (a1.x + a1.y) + (a3.x + a3.y);
        }
    }

    // ---- epilogue: quad reduction for row sums, write ctx ----
#pragma unroll
    for (int mi = 0; mi < 2; mi++) {
#pragma unroll
        for (int ri = 0; ri < 2; ri++) {
            lsumf[mi][ri] += __shfl_xor_sync(0xffffffffu, lsumf[mi][ri], 1);
            lsumf[mi][ri] += __shfl_xor_sync(0xffffffffu, lsumf[mi][ri], 2);
        }
        float i0 = 1.0f / lsumf[mi][0];   // row lr
        float i1 = 1.0f / lsumf[mi][1];   // row lr+8
        size_t row0 = ((size_t)n * SEQ + q0 + mi * 16) * DM + h * DKH;
#pragma unroll
        for (int ng = 0; ng < 8; ng++) {
            int col = ng * 8 + lc;
            *(uint32_t*)(g_ctx + row0 + col)          = pack2h(oacc[mi][ng][0] * i0, oacc[mi][ng][1] * i0);
            *(uint32_t*)(g_ctx + row0 + 8 * DM + col) = pack2h(oacc[mi][ng][2] * i1, oacc[mi][ng][3] * i1);
        }
    }
}

// ===================== launch =====================
extern "C" void kernel_launch(void* const* d_in, const int* in_sizes, int n_in,
                              void* d_out, int out_size)
{
    const float* q   = (const float*)d_in[0];
    const float* k   = (const float*)d_in[1];
    const float* v   = (const float*)d_in[2];
    const int*   msk = (const int*)d_in[3];
    const float* Wq  = (const float*)d_in[4];
    const float* bq  = (const float*)d_in[5];
    const float* Wk  = (const float*)d_in[6];
    const float* bk  = (const float*)d_in[7];
    const float* Wv  = (const float*)d_in[8];
    const float* bv  = (const float*)d_in[9];
    const float* Wo  = (const float*)d_in[10];
    const float* bo  = (const float*)d_in[11];
    float* out = (float*)d_out;

    cudaFuncSetAttribute(proj_qkv_kernel, cudaFuncAttributeMaxDynamicSharedMemorySize, PROJ_SMEM);
    cudaFuncSetAttribute(proj_o_kernel,   cudaFuncAttributeMaxDynamicSharedMemorySize, PROJ_SMEM);
    cudaFuncSetAttribute(attn_kernel,     cudaFuncAttributeMaxDynamicSharedMemorySize, ATT_SMEM);

    // ONE prep launch: converts + mask pack
    prep_kernel<<<(TOT4 + MW + 255) / 256, 256>>>(q, k, v, Wq, Wk, Wv, Wo, msk);

    dim3 pgrid(DM / 128, NB * SEQ / 128, 3);
    proj_qkv_kernel<<<pgrid, 256, PROJ_SMEM>>>(bq, bk, bv);

    attn_kernel<<<dim3(SEQ / 128, NH, NB), 128, ATT_SMEM>>>();

    dim3 ogrid(DM / 128, NB * SEQ / 128);
    proj_o_kernel<<<ogrid, 256, PROJ_SMEM>>>(bo, out);
}